// round 2
// baseline (speedup 1.0000x reference)
#include <cuda_runtime.h>
#include <cuda_bf16.h>

// Problem constants
#define TT   256
#define BB   1000
#define DD   300
#define H4   8
#define NCONS 8            // consumer blocks (last 8 of grid)
#define SUB_ROWS 250       // rows per sub-tile (4 subs per timestep)
#define DCHUNK 100         // d per chunk (3 chunks)
#define XSTRIDE 102        // smem row stride (even for STS.64 align, /2 odd-ish for low LDS conflict)

// smem layout (floats): sW[2400] | sBias[8] pad to 2416 | sx[250*102]
#define SW_OFF   0
#define SB_OFF   2400
#define SX_OFF   2416
#define SMEM_FLOATS (SX_OFF + SUB_ROWS * XSTRIDE)
#define SMEM_BYTES  (SMEM_FLOATS * 4)

__device__ float g_xg[TT * BB * H4];   // xg[t][b][g], 8.192 MB
__device__ int   g_flags[TT];

// packed f32x2 fma: acc += a * b elementwise on packed pairs
__device__ __forceinline__ void fma2(unsigned long long& acc,
                                     unsigned long long a,
                                     unsigned long long b) {
    asm volatile("fma.rn.f32x2 %0, %1, %2, %3;" : "=l"(acc) : "l"(a), "l"(b), "l"(acc));
}
__device__ __forceinline__ unsigned long long pack2(float x) {
    unsigned long long r;
    asm("mov.b64 %0, {%1, %1};" : "=l"(r) : "r"(__float_as_uint(x)));
    return r;
}
__device__ __forceinline__ void unpack2(unsigned long long p, float& lo, float& hi) {
    unsigned a, b;
    asm("mov.b64 {%0, %1}, %2;" : "=r"(a), "=r"(b) : "l"(p));
    lo = __uint_as_float(a);
    hi = __uint_as_float(b);
}

__device__ __forceinline__ void set_flag(int t) {
    asm volatile("st.release.gpu.global.u32 [%0], %1;" :: "l"(&g_flags[t]), "r"(1u) : "memory");
}
__device__ __forceinline__ void wait_flag(int t) {
    unsigned v;
    for (;;) {
        asm volatile("ld.acquire.gpu.global.u32 %0, [%1];" : "=r"(v) : "l"(&g_flags[t]) : "memory");
        if (v) return;
        __nanosleep(64);
    }
}

// fast, overflow-safe activations (~1e-6 accurate)
__device__ __forceinline__ float sigf(float x) {
    x = fminf(fmaxf(x, -30.0f), 30.0f);
    return __fdividef(1.0f, 1.0f + __expf(-x));
}
__device__ __forceinline__ float tanh_(float x) {
    x = fminf(fmaxf(x, -15.0f), 15.0f);
    float e = __expf(-2.0f * x);
    return __fdividef(1.0f - e, 1.0f + e);
}

__global__ void reset_kernel() {
    g_flags[threadIdx.x] = 0;
}

__global__ __launch_bounds__(256) void fused_kernel(
    const float* __restrict__ x,      // [T,B,300]
    const float* __restrict__ Wih0,   // [8,300]
    const float* __restrict__ bih0,
    const float* __restrict__ bhh0,
    const float* __restrict__ h0in,   // [2,B,2]
    const float* __restrict__ c0in,
    const float* __restrict__ Whh0,   // [8,2]
    const float* __restrict__ Wih1,   // [8,2]
    const float* __restrict__ Whh1,   // [8,2]
    const float* __restrict__ bih1,
    const float* __restrict__ bhh1,
    const float* __restrict__ Wlin,   // [1,2]
    const float* __restrict__ blin,
    float* __restrict__ out,          // [B]
    int nprod)
{
    extern __shared__ float smem[];
    const int bid = blockIdx.x;
    const int tid = threadIdx.x;

    if (bid < nprod) {
        // ================= PRODUCER: xg = x @ Wih0^T + (b_ih0+b_hh0) =========
        float* sW = &smem[SW_OFF];      // sW[d*8+g] = Wih0[g*300+d]
        float* sB = &smem[SB_OFF];
        float* sx = &smem[SX_OFF];

        for (int i = tid; i < DD * H4; i += 256) {
            int d = i >> 3, g = i & 7;
            sW[i] = Wih0[g * DD + d];
        }
        if (tid < H4) sB[tid] = bih0[tid] + bhh0[tid];
        __syncthreads();

        const float2* x2 = reinterpret_cast<const float2*>(x);

        for (int t = bid; t < TT; t += nprod) {
            for (int sub = 0; sub < 4; sub++) {
                const int rowbase = t * BB + sub * SUB_ROWS;
                unsigned long long acc0, acc1, acc2, acc3;

                for (int dc = 0; dc < 3; dc++) {
                    __syncthreads();   // protect sx reuse
                    // ---- stage 250 rows x 100 floats, coalesced float2 ----
                    const int base2 = rowbase * (DD / 2) + dc * (DCHUNK / 2);
                    for (int i = tid; i < SUB_ROWS * (DCHUNK / 2); i += 256) {
                        int row = i / (DCHUNK / 2);
                        int c2  = i - row * (DCHUNK / 2);
                        float2 v = x2[base2 + row * (DD / 2) + c2];
                        *reinterpret_cast<float2*>(&sx[row * XSTRIDE + (c2 << 1)]) = v;
                    }
                    __syncthreads();

                    // ---- compute: thread = row, packed f32x2 FMAs ----
                    if (tid < SUB_ROWS) {
                        if (dc == 0) {
                            ulonglong2 b01 = *reinterpret_cast<const ulonglong2*>(&sB[0]);
                            ulonglong2 b23 = *reinterpret_cast<const ulonglong2*>(&sB[4]);
                            acc0 = b01.x; acc1 = b01.y; acc2 = b23.x; acc3 = b23.y;
                        }
                        const float* xr = &sx[tid * XSTRIDE];
                        const ulonglong2* wp =
                            reinterpret_cast<const ulonglong2*>(&sW[dc * DCHUNK * H4]);
                        #pragma unroll 4
                        for (int d = 0; d < DCHUNK; d++) {
                            unsigned long long xp = pack2(xr[d]);
                            ulonglong2 wA = wp[2 * d];
                            ulonglong2 wB = wp[2 * d + 1];
                            fma2(acc0, xp, wA.x);
                            fma2(acc1, xp, wA.y);
                            fma2(acc2, xp, wB.x);
                            fma2(acc3, xp, wB.y);
                        }
                    }
                }
                if (tid < SUB_ROWS) {
                    float4 o0, o1;
                    unpack2(acc0, o0.x, o0.y);
                    unpack2(acc1, o0.z, o0.w);
                    unpack2(acc2, o1.x, o1.y);
                    unpack2(acc3, o1.z, o1.w);
                    float4* dst = reinterpret_cast<float4*>(&g_xg[(size_t)(rowbase + tid) * H4]);
                    dst[0] = o0;
                    dst[1] = o1;
                }
            }
            __threadfence();
            __syncthreads();
            if (tid == 0) set_flag(t);
        }
        return;
    }

    // ================= CONSUMER: 2-layer LSTM recurrence =====================
    if (tid >= 125) return;
    const int b = (bid - nprod) * 125 + tid;   // 8 blocks x 125 = 1000

    float whh0[H4][2], wih1[H4][2], whh1[H4][2], b1[H4];
    #pragma unroll
    for (int g = 0; g < H4; g++) {
        whh0[g][0] = __ldg(&Whh0[g * 2 + 0]);
        whh0[g][1] = __ldg(&Whh0[g * 2 + 1]);
        wih1[g][0] = __ldg(&Wih1[g * 2 + 0]);
        wih1[g][1] = __ldg(&Wih1[g * 2 + 1]);
        whh1[g][0] = __ldg(&Whh1[g * 2 + 0]);
        whh1[g][1] = __ldg(&Whh1[g * 2 + 1]);
        b1[g]      = __ldg(&bih1[g]) + __ldg(&bhh1[g]);
    }
    float wl0 = __ldg(&Wlin[0]), wl1 = __ldg(&Wlin[1]), bl = __ldg(&blin[0]);

    float h0a = h0in[b * 2 + 0],            h0b = h0in[b * 2 + 1];
    float h1a = h0in[BB * 2 + b * 2 + 0],   h1b = h0in[BB * 2 + b * 2 + 1];
    float c0a = c0in[b * 2 + 0],            c0b = c0in[b * 2 + 1];
    float c1a = c0in[BB * 2 + b * 2 + 0],   c1b = c0in[BB * 2 + b * 2 + 1];

    const float4* xg4 = reinterpret_cast<const float4*>(g_xg);
    const int idx0 = b * 2;   // float4 index at t=0

    wait_flag(0);
    float4 v0 = xg4[idx0];
    float4 v1 = xg4[idx0 + 1];

    for (int t = 0; t < TT; t++) {
        float4 n0, n1;
        if (t < TT - 1) {
            wait_flag(t + 1);                       // usually already set
            n0 = xg4[idx0 + (t + 1) * (BB * 2)];    // prefetch, overlapped with MUFU chain
            n1 = xg4[idx0 + (t + 1) * (BB * 2) + 1];
        }

        float pre[H4] = {v0.x, v0.y, v0.z, v0.w, v1.x, v1.y, v1.z, v1.w};

        // ---- layer 0 ----
        #pragma unroll
        for (int g = 0; g < H4; g++)
            pre[g] = fmaf(whh0[g][0], h0a, fmaf(whh0[g][1], h0b, pre[g]));

        float i0 = sigf(pre[0]),  i1 = sigf(pre[1]);
        float f0 = sigf(pre[2]),  f1 = sigf(pre[3]);
        float g0 = tanh_(pre[4]), g1 = tanh_(pre[5]);
        float o0 = sigf(pre[6]),  o1 = sigf(pre[7]);
        c0a = fmaf(f0, c0a, i0 * g0);
        c0b = fmaf(f1, c0b, i1 * g1);
        h0a = o0 * tanh_(c0a);
        h0b = o1 * tanh_(c0b);

        // ---- layer 1 ----
        float pre1[H4];
        #pragma unroll
        for (int g = 0; g < H4; g++) {
            float p = fmaf(wih1[g][0], h0a, fmaf(wih1[g][1], h0b, b1[g]));
            pre1[g] = fmaf(whh1[g][0], h1a, fmaf(whh1[g][1], h1b, p));
        }
        float i0b = sigf(pre1[0]),  i1b = sigf(pre1[1]);
        float f0b = sigf(pre1[2]),  f1b = sigf(pre1[3]);
        float g0b = tanh_(pre1[4]), g1b = tanh_(pre1[5]);
        float o0b = sigf(pre1[6]),  o1b = sigf(pre1[7]);
        c1a = fmaf(f0b, c1a, i0b * g0b);
        c1b = fmaf(f1b, c1b, i1b * g1b);
        h1a = o0b * tanh_(c1a);
        h1b = o1b * tanh_(c1b);

        v0 = n0; v1 = n1;
    }

    out[b] = fmaf(wl0, h1a, fmaf(wl1, h1b, bl));
}

// ---------------------------------------------------------------------------
extern "C" void kernel_launch(void* const* d_in, const int* in_sizes, int n_in,
                              void* d_out, int out_size)
{
    const float* x     = (const float*)d_in[0];
    const float* h0    = (const float*)d_in[1];
    const float* c0    = (const float*)d_in[2];
    const float* Wih0  = (const float*)d_in[3];
    const float* Whh0  = (const float*)d_in[4];
    const float* bih0  = (const float*)d_in[5];
    const float* bhh0  = (const float*)d_in[6];
    const float* Wih1  = (const float*)d_in[7];
    const float* Whh1  = (const float*)d_in[8];
    const float* bih1  = (const float*)d_in[9];
    const float* bhh1  = (const float*)d_in[10];
    const float* Wlin  = (const float*)d_in[11];
    const float* blin  = (const float*)d_in[12];
    float* out = (float*)d_out;

    int dev = 0, nsm = 148;
    cudaGetDevice(&dev);
    cudaDeviceGetAttribute(&nsm, cudaDevAttrMultiProcessorCount, dev);
    if (nsm < NCONS + 16) nsm = NCONS + 16;   // paranoia floor
    int nprod = nsm - NCONS;

    cudaFuncSetAttribute(fused_kernel, cudaFuncAttributeMaxDynamicSharedMemorySize, SMEM_BYTES);

    reset_kernel<<<1, TT>>>();
    fused_kernel<<<nsm, 256, SMEM_BYTES>>>(
        x, Wih0, bih0, bhh0,
        h0, c0, Whh0, Wih1, Whh1, bih1, bhh1, Wlin, blin,
        out, nprod);
}

// round 3
// speedup vs baseline: 1.3476x; 1.3476x over previous
#include <cuda_runtime.h>
#include <cuda_bf16.h>

// Problem constants
#define TT    256
#define BB    1000
#define DD    300
#define H4    8
#define NCONS_BLK 16          // consumer blocks (last 16 of grid)
#define TILE_ROWS 250         // rows per producer task tile (4 tiles per timestep)
#define NTILES    4
#define DCHUNK    100         // cols per chunk (3 chunks of 100)
#define NTASKS    (TT * NTILES)   // 1024

// smem (floats): sW[2400] | sB[8] | pad | sx0[25000] | sx1[25000]
#define SW_FLOATS 2400
#define SX_OFF    2416                    // 16B aligned (2416*4 = 9664)
#define SX_BUF    (TILE_ROWS * DCHUNK)    // 25000 floats = 100000 B
#define SMEM_FLOATS (SX_OFF + 2 * SX_BUF)
#define SMEM_BYTES  (SMEM_FLOATS * 4)     // 209664 B

__device__ float g_xg[TT * BB * H4];   // xg[t][b][g]  (8.192 MB)
__device__ int   g_cnt[TT];            // tiles completed per timestep

// ---------------- PTX helpers ----------------
#define CP_ASYNC16(dst_u32, src_ptr) \
    asm volatile("cp.async.cg.shared.global [%0], [%1], 16;" :: "r"(dst_u32), "l"(src_ptr))
#define CP_COMMIT()  asm volatile("cp.async.commit_group;")
#define CP_WAIT(n)   asm volatile("cp.async.wait_group %0;" :: "n"(n))

__device__ __forceinline__ void fma2(unsigned long long& acc,
                                     unsigned long long a,
                                     unsigned long long b) {
    asm volatile("fma.rn.f32x2 %0, %1, %2, %3;" : "=l"(acc) : "l"(a), "l"(b), "l"(acc));
}
__device__ __forceinline__ unsigned long long pack2(float x) {
    unsigned long long r;
    asm("mov.b64 %0, {%1, %1};" : "=l"(r) : "r"(__float_as_uint(x)));
    return r;
}
__device__ __forceinline__ void unpack2(unsigned long long p, float& lo, float& hi) {
    unsigned a, b;
    asm("mov.b64 {%0, %1}, %2;" : "=r"(a), "=r"(b) : "l"(p));
    lo = __uint_as_float(a);
    hi = __uint_as_float(b);
}

__device__ __forceinline__ void wait_cnt(int t) {
    unsigned v;
    for (;;) {
        asm volatile("ld.acquire.gpu.global.u32 %0, [%1];"
                     : "=r"(v) : "l"(&g_cnt[t]) : "memory");
        if (v >= NTILES) return;
        __nanosleep(32);
    }
}

// fast overflow-safe activations (~1e-6 accurate)
__device__ __forceinline__ float sigf(float x) {
    x = fminf(fmaxf(x, -30.0f), 30.0f);
    return __fdividef(1.0f, 1.0f + __expf(-x));
}
__device__ __forceinline__ float tanh_(float x) {
    x = fminf(fmaxf(x, -15.0f), 15.0f);
    float e = __expf(-2.0f * x);
    return __fdividef(1.0f - e, 1.0f + e);
}

__global__ void reset_kernel() {
    g_cnt[threadIdx.x] = 0;
}

// stage one 250x100 chunk via cp.async (6250 x 16B)
__device__ __forceinline__ void stage_chunk(const float* __restrict__ x,
                                            int rowbase, int dc,
                                            unsigned sdst, int tid) {
    const char* base = reinterpret_cast<const char*>(x)
                     + (size_t)rowbase * (DD * 4) + dc * (DCHUNK * 4);
    for (int i = tid; i < TILE_ROWS * 25; i += 256) {
        int row = i / 25;
        int q   = i - row * 25;
        CP_ASYNC16(sdst + row * 400 + q * 16, base + row * 1200 + q * 16);
    }
    CP_COMMIT();
}

// compute one chunk's contribution for this thread's row
__device__ __forceinline__ void compute_chunk(const float* __restrict__ sx,
                                              const float* __restrict__ sW,
                                              int dc, int tid,
                                              unsigned long long& a0, unsigned long long& a1,
                                              unsigned long long& a2, unsigned long long& a3) {
    const float4* xr = reinterpret_cast<const float4*>(sx + tid * DCHUNK);
    const ulonglong2* wp = reinterpret_cast<const ulonglong2*>(sW + dc * (DCHUNK * H4));
    #pragma unroll 5
    for (int d4 = 0; d4 < 25; d4++) {
        float4 xv = xr[d4];
        {
            unsigned long long xp = pack2(xv.x);
            ulonglong2 wA = wp[d4 * 8 + 0], wB = wp[d4 * 8 + 1];
            fma2(a0, xp, wA.x); fma2(a1, xp, wA.y); fma2(a2, xp, wB.x); fma2(a3, xp, wB.y);
        }
        {
            unsigned long long xp = pack2(xv.y);
            ulonglong2 wA = wp[d4 * 8 + 2], wB = wp[d4 * 8 + 3];
            fma2(a0, xp, wA.x); fma2(a1, xp, wA.y); fma2(a2, xp, wB.x); fma2(a3, xp, wB.y);
        }
        {
            unsigned long long xp = pack2(xv.z);
            ulonglong2 wA = wp[d4 * 8 + 4], wB = wp[d4 * 8 + 5];
            fma2(a0, xp, wA.x); fma2(a1, xp, wA.y); fma2(a2, xp, wB.x); fma2(a3, xp, wB.y);
        }
        {
            unsigned long long xp = pack2(xv.w);
            ulonglong2 wA = wp[d4 * 8 + 6], wB = wp[d4 * 8 + 7];
            fma2(a0, xp, wA.x); fma2(a1, xp, wA.y); fma2(a2, xp, wB.x); fma2(a3, xp, wB.y);
        }
    }
}

__global__ __launch_bounds__(256) void fused_kernel(
    const float* __restrict__ x,      // [T,B,300]
    const float* __restrict__ Wih0,   // [8,300]
    const float* __restrict__ bih0,
    const float* __restrict__ bhh0,
    const float* __restrict__ h0in,   // [2,B,2]
    const float* __restrict__ c0in,
    const float* __restrict__ Whh0,   // [8,2]
    const float* __restrict__ Wih1,   // [8,2]
    const float* __restrict__ Whh1,   // [8,2]
    const float* __restrict__ bih1,
    const float* __restrict__ bhh1,
    const float* __restrict__ Wlin,   // [1,2]
    const float* __restrict__ blin,
    float* __restrict__ out,          // [B]
    int nprod)
{
    extern __shared__ float smem[];
    const int bid = blockIdx.x;
    const int tid = threadIdx.x;

    if (bid < nprod) {
        // =================== PRODUCER ===================
        float* sW  = smem;                 // sW[d*8+g] = Wih0[g*300+d]
        float* sB  = smem + SW_FLOATS;
        float* sx0 = smem + SX_OFF;
        float* sx1 = smem + SX_OFF + SX_BUF;
        unsigned u0 = (unsigned)__cvta_generic_to_shared(sx0);
        unsigned u1 = (unsigned)__cvta_generic_to_shared(sx1);

        for (int i = tid; i < DD * H4; i += 256) {
            int d = i >> 3, g = i & 7;
            sW[i] = Wih0[g * DD + d];
        }
        if (tid < H4) sB[tid] = bih0[tid] + bhh0[tid];
        __syncthreads();

        ulonglong2 bias01 = *reinterpret_cast<const ulonglong2*>(&sB[0]);
        ulonglong2 bias23 = *reinterpret_cast<const ulonglong2*>(&sB[4]);

        for (int task = bid; task < NTASKS; task += nprod) {
            const int t       = task >> 2;
            const int tile    = task & 3;
            const int rowbase = t * BB + tile * TILE_ROWS;

            unsigned long long a0 = bias01.x, a1 = bias01.y;
            unsigned long long a2 = bias23.x, a3 = bias23.y;

            stage_chunk(x, rowbase, 0, u0, tid);     // G0 -> buf0
            stage_chunk(x, rowbase, 1, u1, tid);     // G1 -> buf1
            CP_WAIT(1);                              // c0 done
            __syncthreads();
            if (tid < TILE_ROWS) compute_chunk(sx0, sW, 0, tid, a0, a1, a2, a3);
            __syncthreads();                         // all done reading buf0
            stage_chunk(x, rowbase, 2, u0, tid);     // G2 -> buf0
            CP_WAIT(1);                              // c1 done
            __syncthreads();
            if (tid < TILE_ROWS) compute_chunk(sx1, sW, 1, tid, a0, a1, a2, a3);
            CP_WAIT(0);                              // c2 done
            __syncthreads();
            if (tid < TILE_ROWS) {
                compute_chunk(sx0, sW, 2, tid, a0, a1, a2, a3);
                float4 o0, o1;
                unpack2(a0, o0.x, o0.y);
                unpack2(a1, o0.z, o0.w);
                unpack2(a2, o1.x, o1.y);
                unpack2(a3, o1.z, o1.w);
                float4* dst = reinterpret_cast<float4*>(&g_xg[(size_t)(rowbase + tid) * H4]);
                dst[0] = o0;
                dst[1] = o1;
            }
            __threadfence();
            __syncthreads();                         // reads of buf0 done; stores fenced
            if (tid == 0) atomicAdd(&g_cnt[t], 1);
        }
        return;
    }

    // =================== CONSUMER ===================
    // 16 blocks x 4 warps (threads 0..127). Lanes 0-15: layer0 of 16 elements,
    // lanes 16-31: layer1 of the same elements, lagged one timestep.
    if (tid >= 128) return;
    const int warp = tid >> 5;
    const int lane = tid & 31;
    const bool l1  = (lane >= 16);
    const int e    = ((bid - nprod) * 4 + warp) * 16 + (lane & 15);
    const int b    = (e < BB) ? e : (BB - 1);

    // Uniform-coefficient registers: pre[g] = vb[g] + C[g]·hp + A[g]·h
    float A0[H4], A1[H4], C0[H4], C1[H4], vb[H4];
    float ha, hb, ca, cb;
    float hpa = 0.0f, hpb = 0.0f;

    if (!l1) {
        #pragma unroll
        for (int g = 0; g < H4; g++) {
            A0[g] = __ldg(&Whh0[g * 2 + 0]);
            A1[g] = __ldg(&Whh0[g * 2 + 1]);
            C0[g] = 0.0f;
            C1[g] = 0.0f;
            vb[g] = 0.0f;                       // overwritten by xg load
        }
        ha = h0in[b * 2 + 0]; hb = h0in[b * 2 + 1];
        ca = c0in[b * 2 + 0]; cb = c0in[b * 2 + 1];
    } else {
        #pragma unroll
        for (int g = 0; g < H4; g++) {
            A0[g] = __ldg(&Whh1[g * 2 + 0]);
            A1[g] = __ldg(&Whh1[g * 2 + 1]);
            C0[g] = __ldg(&Wih1[g * 2 + 0]);
            C1[g] = __ldg(&Wih1[g * 2 + 1]);
            vb[g] = __ldg(&bih1[g]) + __ldg(&bhh1[g]);   // constant base
        }
        ha = h0in[BB * 2 + b * 2 + 0]; hb = h0in[BB * 2 + b * 2 + 1];
        ca = c0in[BB * 2 + b * 2 + 0]; cb = c0in[BB * 2 + b * 2 + 1];
    }
    const float wl0 = __ldg(&Wlin[0]), wl1 = __ldg(&Wlin[1]), bl = __ldg(&blin[0]);

    const float4* xg4 = reinterpret_cast<const float4*>(g_xg);
    const int idx0 = b * 2;

    wait_cnt(0);
    if (!l1) {
        float4 v0 = xg4[idx0];
        float4 v1 = xg4[idx0 + 1];
        vb[0] = v0.x; vb[1] = v0.y; vb[2] = v0.z; vb[3] = v0.w;
        vb[4] = v1.x; vb[5] = v1.y; vb[6] = v1.z; vb[7] = v1.w;
    }

    for (int s = 0; s <= TT; s++) {
        // prefetch xg(s+1) for layer0 lanes
        float4 n0, n1;
        const bool pf = (s + 1 < TT);
        if (pf) {
            wait_cnt(s + 1);
            if (!l1) {
                n0 = xg4[idx0 + (s + 1) * (BB * 2)];
                n1 = xg4[idx0 + (s + 1) * (BB * 2) + 1];
            }
        }

        // uniform gate computation (identical instructions for both layer lanes)
        float pre[H4];
        #pragma unroll
        for (int g = 0; g < H4; g++)
            pre[g] = fmaf(C0[g], hpa, fmaf(C1[g], hpb, vb[g]));
        #pragma unroll
        for (int g = 0; g < H4; g++)
            pre[g] = fmaf(A0[g], ha, fmaf(A1[g], hb, pre[g]));

        float i0 = sigf(pre[0]),  i1 = sigf(pre[1]);
        float f0 = sigf(pre[2]),  f1 = sigf(pre[3]);
        float g0 = tanh_(pre[4]), g1 = tanh_(pre[5]);
        float o0 = sigf(pre[6]),  o1 = sigf(pre[7]);
        float nca = fmaf(f0, ca, i0 * g0);
        float ncb = fmaf(f1, cb, i1 * g1);
        float nha = o0 * tanh_(nca);
        float nhb = o1 * tanh_(ncb);

        const bool valid = l1 ? (s >= 1) : (s < TT);
        if (valid) { ca = nca; cb = ncb; ha = nha; hb = nhb; }

        // pass layer0's h(s) to layer1 partner (used at s+1 for t=s)
        hpa = __shfl_up_sync(0xffffffffu, ha, 16);
        hpb = __shfl_up_sync(0xffffffffu, hb, 16);

        if (pf && !l1) {
            vb[0] = n0.x; vb[1] = n0.y; vb[2] = n0.z; vb[3] = n0.w;
            vb[4] = n1.x; vb[5] = n1.y; vb[6] = n1.z; vb[7] = n1.w;
        }
    }

    if (l1 && e < BB)
        out[b] = fmaf(wl0, ha, fmaf(wl1, hb, bl));
}

// ---------------------------------------------------------------------------
extern "C" void kernel_launch(void* const* d_in, const int* in_sizes, int n_in,
                              void* d_out, int out_size)
{
    const float* x     = (const float*)d_in[0];
    const float* h0    = (const float*)d_in[1];
    const float* c0    = (const float*)d_in[2];
    const float* Wih0  = (const float*)d_in[3];
    const float* Whh0  = (const float*)d_in[4];
    const float* bih0  = (const float*)d_in[5];
    const float* bhh0  = (const float*)d_in[6];
    const float* Wih1  = (const float*)d_in[7];
    const float* Whh1  = (const float*)d_in[8];
    const float* bih1  = (const float*)d_in[9];
    const float* bhh1  = (const float*)d_in[10];
    const float* Wlin  = (const float*)d_in[11];
    const float* blin  = (const float*)d_in[12];
    float* out = (float*)d_out;

    int dev = 0, nsm = 148;
    cudaGetDevice(&dev);
    cudaDeviceGetAttribute(&nsm, cudaDevAttrMultiProcessorCount, dev);
    if (nsm < NCONS_BLK + 8) nsm = NCONS_BLK + 8;
    int nprod = nsm - NCONS_BLK;

    cudaFuncSetAttribute(fused_kernel, cudaFuncAttributeMaxDynamicSharedMemorySize, SMEM_BYTES);

    reset_kernel<<<1, TT>>>();
    fused_kernel<<<nsm, 256, SMEM_BYTES>>>(
        x, Wih0, bih0, bhh0,
        h0, c0, Whh0, Wih1, Whh1, bih1, bhh1, Wlin, blin,
        out, nprod);
}